// round 3
// baseline (speedup 1.0000x reference)
#include <cuda_runtime.h>
#include <cuda_bf16.h>

// GRU: B=2048, T=256, F=128, H=64, G=192.
// 128 blocks x 256 threads. Block = 16 batch rows.
// Thread layout: ks = tid&1 (K-half), u = (tid>>1)&63, rg = tid>>7 (8 rows).
// Each thread accumulates 8 rows x 3 gates over its K-half via fma.rn.f32x2,
// then reduces across the ks lane-pair with one shfl.xor.

#define Bn 2048
#define Tn 256
#define Fn 128
#define Hn 64
#define Gn 192
#define ROWS 16
#define NTH 256

// SMEM layout in 16B (float4) units:
//  w_ih: 192 x 34 (128 fl + 8 pad)  -> 6528   (stride 34 => conflict-free (u,ks) LDS)
//  w_hh: 192 x 18 (64 fl + 8 pad)   -> 3456
//  x   : 2 x 16 x 33                -> 1056
//  h   : 2 x 16 x 17                ->  544
#define WIH_OFF 0
#define WIH_STR 34
#define WHH_OFF 6528
#define WHH_STR 18
#define XB_OFF  9984
#define XROW_STR 33
#define HB_OFF  11040
#define HROW_STR 17
#define XBUF_F4 528
#define HBUF_F4 272
#define SMEM_F4 11584
#define SMEM_BYTES (SMEM_F4 * 16)

typedef unsigned long long u64t;

__device__ __forceinline__ void fma2(u64t& d, u64t a, u64t b) {
    asm("fma.rn.f32x2 %0, %1, %2, %0;" : "+l"(d) : "l"(a), "l"(b));
}
__device__ __forceinline__ float hsum(u64t v) {
    float2 f;
    asm("mov.b64 {%0, %1}, %2;" : "=f"(f.x), "=f"(f.y) : "l"(v));
    return f.x + f.y;
}
__device__ __forceinline__ float sigmoidf_(float x) {
    return 1.0f / (1.0f + __expf(-x));
}
__device__ __forceinline__ float tanh_ap(float x) {
    float r;
    asm("tanh.approx.f32 %0, %1;" : "=f"(r) : "f"(x));
    return r;
}

__global__ void __launch_bounds__(NTH, 1)
gru_fused_kernel(const float* __restrict__ x,
                 const float* __restrict__ w_ih,
                 const float* __restrict__ w_hh,
                 const float* __restrict__ b_ih,
                 const float* __restrict__ b_hh,
                 const float* __restrict__ fc_w,
                 const float* __restrict__ fc_b,
                 float* __restrict__ out) {
    extern __shared__ float4 sm4[];

    const int tid = threadIdx.x;
    const int ks  = tid & 1;             // K-half (even/odd 16B chunks)
    const int u   = (tid >> 1) & 63;     // hidden unit
    const int rg  = tid >> 7;            // 0/1 -> rows rg*8 .. rg*8+7
    const int r0  = blockIdx.x * ROWS;

    // ---- weights -> SMEM (padded strides) ----
    {
        const float4* g4 = (const float4*)w_ih;   // 192 x 32 f4
        for (int i = tid; i < Gn * (Fn / 4); i += NTH) {
            int g = i >> 5, k4 = i & 31;
            sm4[WIH_OFF + g * WIH_STR + k4] = g4[i];
        }
        const float4* h4 = (const float4*)w_hh;   // 192 x 16 f4
        for (int i = tid; i < Gn * (Hn / 4); i += NTH) {
            int g = i >> 4, k4 = i & 15;
            sm4[WHH_OFF + g * WHH_STR + k4] = h4[i];
        }
        float4 z = make_float4(0.f, 0.f, 0.f, 0.f);
        for (int i = tid; i < 2 * HBUF_F4; i += NTH)
            sm4[HB_OFF + i] = z;
    }

    // combined biases
    const float brz_r = b_ih[u]      + b_hh[u];
    const float brz_z = b_ih[64 + u] + b_hh[64 + u];
    const float bn_x  = b_ih[128 + u];
    const float bn_h  = b_hh[128 + u];

    // x prefetch indexing: 512 f4/tile, 2 per thread
    const int pf_row = tid >> 4;          // 16 rows
    const int pf_k0  = tid & 15;          // f4 index, +16 for second
    const float* pf_base = x + (size_t)(r0 + pf_row) * Tn * Fn + pf_k0 * 4;

    // ---- preload x for t=0 ----
    {
        const float4* src = (const float4*)pf_base;
        sm4[XB_OFF + pf_row * XROW_STR + pf_k0]      = src[0];
        sm4[XB_OFF + pf_row * XROW_STR + pf_k0 + 16] = src[16];
    }
    __syncthreads();

    // weight row pointers (f4-indexed, cast to 16B loads)
    const float4* wrp = sm4 + WIH_OFF + (size_t)u * WIH_STR;
    const float4* wzp = sm4 + WIH_OFF + (size_t)(64 + u) * WIH_STR;
    const float4* wnp = sm4 + WIH_OFF + (size_t)(128 + u) * WIH_STR;
    const float4* vrp = sm4 + WHH_OFF + (size_t)u * WHH_STR;
    const float4* vzp = sm4 + WHH_OFF + (size_t)(64 + u) * WHH_STR;
    const float4* vnp = sm4 + WHH_OFF + (size_t)(128 + u) * WHH_STR;

    for (int t = 0; t < Tn; ++t) {
        float4 p0, p1;
        const bool pf = (t + 1 < Tn);
        if (pf) {
            const float4* src = (const float4*)(pf_base + (size_t)(t + 1) * Fn);
            p0 = src[0];
            p1 = src[16];
        }

        const float4* xb = sm4 + XB_OFF + (t & 1) * XBUF_F4 + (rg * 8) * XROW_STR;
        const float4* hb = sm4 + HB_OFF + (t & 1) * HBUF_F4 + (rg * 8) * HROW_STR;
        const float* hcur = (const float*)(sm4 + HB_OFF + (t & 1) * HBUF_F4);
        float* hnext      = (float*)(sm4 + HB_OFF + ((t + 1) & 1) * HBUF_F4);

        u64t aR[8], aZ[8], aNx[8], aNh[8];
        #pragma unroll
        for (int r = 0; r < 8; ++r) { aR[r]=0ull; aZ[r]=0ull; aNx[r]=0ull; aNh[r]=0ull; }

        // ---- gx: this thread handles chunks c = 2j+ks, j=0..15 ----
        #pragma unroll 4
        for (int j = 0; j < 16; ++j) {
            const int c = 2 * j + ks;
            ulonglong2 a = *(const ulonglong2*)(wrp + c);
            ulonglong2 b = *(const ulonglong2*)(wzp + c);
            ulonglong2 cc = *(const ulonglong2*)(wnp + c);
            #pragma unroll
            for (int r = 0; r < 8; ++r) {
                ulonglong2 xv = *(const ulonglong2*)(xb + r * XROW_STR + c);
                fma2(aR[r],  xv.x, a.x);  fma2(aR[r],  xv.y, a.y);
                fma2(aZ[r],  xv.x, b.x);  fma2(aZ[r],  xv.y, b.y);
                fma2(aNx[r], xv.x, cc.x); fma2(aNx[r], xv.y, cc.y);
            }
        }

        // store prefetched x into the other buffer
        if (pf) {
            float4* xn = sm4 + XB_OFF + ((t + 1) & 1) * XBUF_F4 + pf_row * XROW_STR;
            xn[pf_k0]      = p0;
            xn[pf_k0 + 16] = p1;
        }

        // ---- gh: chunks c = 2j+ks, j=0..7 ----
        #pragma unroll 4
        for (int j = 0; j < 8; ++j) {
            const int c = 2 * j + ks;
            ulonglong2 a = *(const ulonglong2*)(vrp + c);
            ulonglong2 b = *(const ulonglong2*)(vzp + c);
            ulonglong2 cc = *(const ulonglong2*)(vnp + c);
            #pragma unroll
            for (int r = 0; r < 8; ++r) {
                ulonglong2 hv = *(const ulonglong2*)(hb + r * HROW_STR + c);
                fma2(aR[r],  hv.x, a.x);  fma2(aR[r],  hv.y, a.y);
                fma2(aZ[r],  hv.x, b.x);  fma2(aZ[r],  hv.y, b.y);
                fma2(aNh[r], hv.x, cc.x); fma2(aNh[r], hv.y, cc.y);
            }
        }

        // ---- reduce across ks lane-pair, gates, h update ----
        #pragma unroll
        for (int r = 0; r < 8; ++r) {
            int row = rg * 8 + r;
            float sR  = hsum(aR[r]);
            float sZ  = hsum(aZ[r]);
            float sNx = hsum(aNx[r]);
            float sNh = hsum(aNh[r]);
            sR  += __shfl_xor_sync(0xffffffffu, sR, 1);
            sZ  += __shfl_xor_sync(0xffffffffu, sZ, 1);
            sNx += __shfl_xor_sync(0xffffffffu, sNx, 1);
            sNh += __shfl_xor_sync(0xffffffffu, sNh, 1);
            float hold = hcur[row * 68 + u];
            float rr = sigmoidf_(sR + brz_r);
            float zz = sigmoidf_(sZ + brz_z);
            float nn = tanh_ap(sNx + bn_x + rr * (sNh + bn_h));
            float hv = (1.0f - zz) * nn + zz * hold;
            if (ks == 0)
                hnext[row * 68 + u] = hv;
        }

        __syncthreads();
    }

    // ---- final FC ----
    if (tid < ROWS) {
        const float* hf = (const float*)(sm4 + HB_OFF + (Tn & 1) * HBUF_F4);
        float s = fc_b[0];
        #pragma unroll 8
        for (int j = 0; j < Hn; ++j)
            s += hf[tid * 68 + j] * fc_w[j];
        out[r0 + tid] = s;
    }
}

extern "C" void kernel_launch(void* const* d_in, const int* in_sizes, int n_in,
                              void* d_out, int out_size) {
    const float* x    = (const float*)d_in[0];
    const float* w_ih = (const float*)d_in[1];
    const float* w_hh = (const float*)d_in[2];
    const float* b_ih = (const float*)d_in[3];
    const float* b_hh = (const float*)d_in[4];
    const float* fc_w = (const float*)d_in[5];
    const float* fc_b = (const float*)d_in[6];
    float* out = (float*)d_out;

    cudaFuncSetAttribute(gru_fused_kernel,
                         cudaFuncAttributeMaxDynamicSharedMemorySize, SMEM_BYTES);
    gru_fused_kernel<<<Bn / ROWS, NTH, SMEM_BYTES>>>(
        x, w_ih, w_hh, b_ih, b_hh, fc_w, fc_b, out);
}

// round 5
// speedup vs baseline: 1.3674x; 1.3674x over previous
#include <cuda_runtime.h>
#include <cuda_bf16.h>
#include <cstdint>

// ============================================================================
// GRU: B=2048, T=256, F=128, H=64, G=192.
// Phase 1: gx = x @ w_ih^T + b_ih via mma.sync bf16 (3-term hi/lo split).
// Phase 2: recurrence h_t = GRU(h_{t-1}, gx_t) in SIMT fp32 at FFMA roofline.
// ============================================================================

#define Bn 2048
#define Tn 256
#define Fn 128
#define Hn 64
#define Gn 192
#define BT (Bn * Tn)          // 524288 rows
#define TILES (BT / 128)      // 4096 M-tiles of 128 rows
#define TPB 8                 // tiles per block
#define GRID1 (TILES / TPB)   // 512 blocks

__device__ float g_gx[(size_t)BT * Gn];   // 402 MB scratch

// ---------------------------------------------------------------------------
// Phase 1: HMMA GEMM
// ---------------------------------------------------------------------------
// SMEM (bytes): rows padded to 272B (17 x 16B -> conflict-free ldmatrix)
#define SM_AH 0          // x hi  : 128 x 272
#define SM_AL 34816      // x lo
#define SM_BH 69632      // w hi  : 192 x 272
#define SM_BL 121856     // w lo
#define SM_BIAS 174080   // 192 f32
#define SMEM1 174848

__device__ __forceinline__ uint32_t smem_u32(const void* p) {
    uint32_t a;
    asm("{ .reg .u64 t; cvta.to.shared.u64 t, %1; cvt.u32.u64 %0, t; }"
        : "=r"(a) : "l"(p));
    return a;
}

__device__ __forceinline__ void ldsm4(uint32_t* r, uint32_t addr) {
    asm volatile("ldmatrix.sync.aligned.m8n8.x4.shared.b16 {%0,%1,%2,%3}, [%4];"
        : "=r"(r[0]), "=r"(r[1]), "=r"(r[2]), "=r"(r[3]) : "r"(addr));
}

__device__ __forceinline__ void mma16816(float* c, const uint32_t* a,
                                         uint32_t b0, uint32_t b1) {
    asm volatile(
        "mma.sync.aligned.m16n8k16.row.col.f32.bf16.bf16.f32 "
        "{%0,%1,%2,%3}, {%4,%5,%6,%7}, {%8,%9}, {%0,%1,%2,%3};"
        : "+f"(c[0]), "+f"(c[1]), "+f"(c[2]), "+f"(c[3])
        : "r"(a[0]), "r"(a[1]), "r"(a[2]), "r"(a[3]), "r"(b0), "r"(b1));
}

// split fp32x4 into bf16 hi + bf16 lo, store 8B each into padded smem rows
__device__ __forceinline__ void split_store(char* sm, int off_hi, int off_lo,
                                            int boff, float4 v) {
    __nv_bfloat162 h01 = __floats2bfloat162_rn(v.x, v.y);
    __nv_bfloat162 h23 = __floats2bfloat162_rn(v.z, v.w);
    *(uint2*)(sm + off_hi + boff) =
        make_uint2(*(uint32_t*)&h01, *(uint32_t*)&h23);
    float l0 = v.x - __bfloat162float(__low2bfloat16(h01));
    float l1 = v.y - __bfloat162float(__high2bfloat16(h01));
    float l2 = v.z - __bfloat162float(__low2bfloat16(h23));
    float l3 = v.w - __bfloat162float(__high2bfloat16(h23));
    __nv_bfloat162 s01 = __floats2bfloat162_rn(l0, l1);
    __nv_bfloat162 s23 = __floats2bfloat162_rn(l2, l3);
    *(uint2*)(sm + off_lo + boff) =
        make_uint2(*(uint32_t*)&s01, *(uint32_t*)&s23);
}

__global__ void __launch_bounds__(256, 1)
gx_gemm(const float* __restrict__ x,
        const float* __restrict__ w_ih,
        const float* __restrict__ b_ih) {
    extern __shared__ char sm[];
    const uint32_t sb = smem_u32(sm);
    const int tid = threadIdx.x;
    const int w   = tid >> 5;
    const int l   = tid & 31;

    // ---- w_ih -> B hi/lo (192 x 32 f4) ----
    {
        const float4* w4 = (const float4*)w_ih;
        #pragma unroll
        for (int j = 0; j < 24; ++j) {
            int idx = j * 256 + tid;
            int row = idx >> 5, c4 = idx & 31;
            split_store(sm, SM_BH, SM_BL, row * 272 + c4 * 8, w4[idx]);
        }
    }
    if (tid < Gn) ((float*)(sm + SM_BIAS))[tid] = b_ih[tid];

    // ---- prefetch tile 0 into registers ----
    const float4* x4 = (const float4*)x;
    float4 p[16];
    {
        size_t tb = (size_t)blockIdx.x * TPB * 4096;
        #pragma unroll
        for (int j = 0; j < 16; ++j) p[j] = x4[tb + j * 256 + tid];
    }

    // ldmatrix lane address parts
    const int mrow  = (l & 7) + ((l >> 3) & 1) * 8;   // 0..15
    const int khalf = (l >> 4) & 1;                   // 0/1 -> +8 cols
    const uint32_t a_lane = (uint32_t)((w * 16 + mrow) * 272 + khalf * 16);
    const uint32_t b_lane = (uint32_t)(mrow * 272 + khalf * 16);

    const int c_l = 2 * (l & 3);
    const int r_l = l >> 2;
    const float* bias = (const float*)(sm + SM_BIAS);

    for (int it = 0; it < TPB; ++it) {
        // ---- convert prefetched x tile into A hi/lo smem ----
        #pragma unroll
        for (int j = 0; j < 16; ++j) {
            int idx = j * 256 + tid;
            int row = idx >> 5, c4 = idx & 31;
            split_store(sm, SM_AH, SM_AL, row * 272 + c4 * 8, p[j]);
        }
        __syncthreads();

        // ---- prefetch next tile ----
        if (it + 1 < TPB) {
            size_t tb = ((size_t)blockIdx.x * TPB + it + 1) * 4096;
            #pragma unroll
            for (int j = 0; j < 16; ++j) p[j] = x4[tb + j * 256 + tid];
        }

        float acc[24][4];
        #pragma unroll
        for (int nt = 0; nt < 24; ++nt)
            #pragma unroll
            for (int q = 0; q < 4; ++q) acc[nt][q] = 0.0f;

        // ---- K loop: 8 steps of k16 ----
        #pragma unroll
        for (int ks = 0; ks < 8; ++ks) {
            uint32_t ah[4], al[4];
            ldsm4(ah, sb + SM_AH + a_lane + ks * 32);
            ldsm4(al, sb + SM_AL + a_lane + ks * 32);
            #pragma unroll
            for (int np = 0; np < 12; ++np) {
                uint32_t bh[4], bl[4];
                uint32_t bo = b_lane + (uint32_t)(np * 16 * 272 + ks * 32);
                ldsm4(bh, sb + SM_BH + bo);
                ldsm4(bl, sb + SM_BL + bo);
                mma16816(acc[2 * np],     ah, bh[0], bh[2]);
                mma16816(acc[2 * np + 1], ah, bh[1], bh[3]);
                mma16816(acc[2 * np],     ah, bl[0], bl[2]);
                mma16816(acc[2 * np + 1], ah, bl[1], bl[3]);
                mma16816(acc[2 * np],     al, bh[0], bh[2]);
                mma16816(acc[2 * np + 1], al, bh[1], bh[3]);
            }
        }

        // ---- epilogue: +bias, store to g_gx ----
        const int tile = blockIdx.x * TPB + it;
        const size_t row0 = (size_t)tile * 128 + w * 16 + r_l;
        #pragma unroll
        for (int nt = 0; nt < 24; ++nt) {
            int c0 = nt * 8 + c_l;
            float2 bb = *(const float2*)(bias + c0);
            float2 o0 = make_float2(acc[nt][0] + bb.x, acc[nt][1] + bb.y);
            float2 o1 = make_float2(acc[nt][2] + bb.x, acc[nt][3] + bb.y);
            *(float2*)(g_gx + row0 * 192 + c0)       = o0;
            *(float2*)(g_gx + (row0 + 8) * 192 + c0) = o1;
        }
        __syncthreads();
    }
}

// ---------------------------------------------------------------------------
// Phase 2: recurrence. 128 blocks x 256 threads, 16 rows/block.
// ---------------------------------------------------------------------------
#define ROWS 16
#define NTH2 256

// SMEM f4 layout
#define WHH_OFF 0        // 192 x 17 -> 3264
#define GX_OFF  3264     // 2 x 16 x 48 -> 1536
#define HB_OFF  4800     // 2 x 16 x 17 -> 544
#define GXBUF 768
#define HBUF 272
#define SMEM2 (5344 * 16)

__device__ __forceinline__ float sigmoidf_(float v) {
    return 1.0f / (1.0f + __expf(-v));
}
__device__ __forceinline__ float tanh_ap(float v) {
    float r;
    asm("tanh.approx.f32 %0, %1;" : "=f"(r) : "f"(v));
    return r;
}

__global__ void __launch_bounds__(NTH2, 1)
gru_rec(const float* __restrict__ w_hh,
        const float* __restrict__ b_hh,
        const float* __restrict__ fc_w,
        const float* __restrict__ fc_b,
        float* __restrict__ out) {
    extern __shared__ float4 sm4[];

    const int tid = threadIdx.x;
    const int u   = tid & 63;
    const int rg  = tid >> 6;          // 0..3 -> rows rg*4..rg*4+3
    const int r0  = blockIdx.x * ROWS;

    // w_hh -> SMEM (192 x 16 f4, stride 17)
    {
        const float4* h4 = (const float4*)w_hh;
        for (int i = tid; i < Gn * (Hn / 4); i += NTH2) {
            int g = i >> 4, k4 = i & 15;
            sm4[WHH_OFF + g * 17 + k4] = h4[i];
        }
        float4 z = make_float4(0.f, 0.f, 0.f, 0.f);
        for (int i = tid; i < 2 * HBUF; i += NTH2)
            sm4[HB_OFF + i] = z;
    }

    const float bhr = b_hh[u], bhz = b_hh[64 + u], bhn = b_hh[128 + u];

    // gx prefetch mapping: 768 f4/step-tile, 3 per thread
    int pfr[3], pfc[3];
    #pragma unroll
    for (int k = 0; k < 3; ++k) {
        int idx = tid + 256 * k;
        pfr[k] = idx / 48;
        pfc[k] = idx % 48;
    }
    const float4* gx4 = (const float4*)g_gx;

    #pragma unroll
    for (int k = 0; k < 3; ++k)
        sm4[GX_OFF + tid + 256 * k] =
            gx4[((size_t)(r0 + pfr[k]) * Tn + 0) * 48 + pfc[k]];
    __syncthreads();

    const float4* vr = sm4 + WHH_OFF + u * 17;
    const float4* vz = sm4 + WHH_OFF + (64 + u) * 17;
    const float4* vn = sm4 + WHH_OFF + (128 + u) * 17;

    for (int t = 0; t < Tn; ++t) {
        float4 p[3];
        const bool pf = (t + 1 < Tn);
        if (pf) {
            #pragma unroll
            for (int k = 0; k < 3; ++k)
                p[k] = gx4[((size_t)(r0 + pfr[k]) * Tn + (t + 1)) * 48 + pfc[k]];
        }

        const float4* hb = sm4 + HB_OFF + (t & 1) * HBUF;
        const float* hcur = (const float*)hb;
        float* hnext = (float*)(sm4 + HB_OFF + ((t + 1) & 1) * HBUF);

        float ahr[4], ahz[4], ahn[4];
        #pragma unroll
        for (int r = 0; r < 4; ++r) { ahr[r] = bhr; ahz[r] = bhz; ahn[r] = bhn; }

        const float4* hrow0 = hb + (rg * 4 + 0) * 17;
        const float4* hrow1 = hb + (rg * 4 + 1) * 17;
        const float4* hrow2 = hb + (rg * 4 + 2) * 17;
        const float4* hrow3 = hb + (rg * 4 + 3) * 17;

        #pragma unroll 4
        for (int kq = 0; kq < 16; ++kq) {
            float4 a = vr[kq], b = vz[kq], c = vn[kq];
            float4 hv;
            hv = hrow0[kq];
            ahr[0] += hv.x*a.x + hv.y*a.y + hv.z*a.z + hv.w*a.w;
            ahz[0] += hv.x*b.x + hv.y*b.y + hv.z*b.z + hv.w*b.w;
            ahn[0] += hv.x*c.x + hv.y*c.y + hv.z*c.z + hv.w*c.w;
            hv = hrow1[kq];
            ahr[1] += hv.x*a.x + hv.y*a.y + hv.z*a.z + hv.w*a.w;
            ahz[1] += hv.x*b.x + hv.y*b.y + hv.z*b.z + hv.w*b.w;
            ahn[1] += hv.x*c.x + hv.y*c.y + hv.z*c.z + hv.w*c.w;
            hv = hrow2[kq];
            ahr[2] += hv.x*a.x + hv.y*a.y + hv.z*a.z + hv.w*a.w;
            ahz[2] += hv.x*b.x + hv.y*b.y + hv.z*b.z + hv.w*b.w;
            ahn[2] += hv.x*c.x + hv.y*c.y + hv.z*c.z + hv.w*c.w;
            hv = hrow3[kq];
            ahr[3] += hv.x*a.x + hv.y*a.y + hv.z*a.z + hv.w*a.w;
            ahz[3] += hv.x*b.x + hv.y*b.y + hv.z*b.z + hv.w*b.w;
            ahn[3] += hv.x*c.x + hv.y*c.y + hv.z*c.z + hv.w*c.w;
        }

        if (pf) {
            float4* gxn = sm4 + GX_OFF + ((t + 1) & 1) * GXBUF;
            #pragma unroll
            for (int k = 0; k < 3; ++k)
                gxn[tid + 256 * k] = p[k];
        }

        const float* gxs = (const float*)(sm4 + GX_OFF + (t & 1) * GXBUF);
        #pragma unroll
        for (int r = 0; r < 4; ++r) {
            int row = rg * 4 + r;
            float gr = gxs[row * 192 + u];
            float gz = gxs[row * 192 + 64 + u];
            float gn = gxs[row * 192 + 128 + u];
            float hold = hcur[row * 68 + u];
            float rr = sigmoidf_(gr + ahr[r]);
            float zz = sigmoidf_(gz + ahz[r]);
            float nn = tanh_ap(gn + rr * ahn[r]);
            hnext[row * 68 + u] = (1.0f - zz) * nn + zz * hold;
        }

        __syncthreads();
    }

    if (tid < ROWS) {
        const float* hf = (const float*)(sm4 + HB_OFF + (Tn & 1) * HBUF);
        float s = fc_b[0];
        #pragma unroll 8
        for (int j = 0; j < Hn; ++j)
            s += hf[tid * 68 + j] * fc_w[j];
        out[r0 + tid] = s;
    }
}

extern "C" void kernel_launch(void* const* d_in, const int* in_sizes, int n_in,
                              void* d_out, int out_size) {
    const float* x    = (const float*)d_in[0];
    const float* w_ih = (const float*)d_in[1];
    const float* w_hh = (const float*)d_in[2];
    const float* b_ih = (const float*)d_in[3];
    const float* b_hh = (const float*)d_in[4];
    const float* fc_w = (const float*)d_in[5];
    const float* fc_b = (const float*)d_in[6];
    float* out = (float*)d_out;

    cudaFuncSetAttribute(gx_gemm,
                         cudaFuncAttributeMaxDynamicSharedMemorySize, SMEM1);
    cudaFuncSetAttribute(gru_rec,
                         cudaFuncAttributeMaxDynamicSharedMemorySize, SMEM2);

    gx_gemm<<<GRID1, 256, SMEM1>>>(x, w_ih, b_ih);
    gru_rec<<<Bn / ROWS, NTH2, SMEM2>>>(w_hh, b_hh, fc_w, fc_b, out);
}

// round 6
// speedup vs baseline: 2.9521x; 2.1589x over previous
#include <cuda_runtime.h>
#include <cuda_bf16.h>
#include <cstdint>

// ============================================================================
// Fully-fused tensor-core GRU. B=2048, T=256, F=128, H=64, G=192.
// 128 blocks x 256 threads; block = 16 batch rows, full recurrence.
// Both x@w_ih^T and h@w_hh^T run on HMMA bf16 with 3-term hi/lo split
// (Ah*Bh + Ah*Bl + Al*Bh). Weight B-fragments resident in registers.
// ============================================================================

#define Bn 2048
#define Tn 256
#define Fn 128
#define Hn 64
#define ROWS 16
#define NTH 256

// smem offsets (bytes)
#define WIH_H 0                 // 192 x 272
#define WIH_L 52224
#define WHH_H 104448            // 192 x 144
#define WHH_L 132096
#define XB    159744            // x bf16: hi bufs [2] then lo bufs [2], 4352 each
#define XSZ   4352
#define XLO   8704              // offset from XB to lo region
#define HBB   177152            // h bf16: hi bufs [2] then lo bufs [2], 2304 each
#define HSZ   2304
#define HLO   4608
#define HF    186368            // fp32 h_last: 16 x 68 floats
#define SMEMB 190720

__device__ __forceinline__ uint32_t smem_u32(const void* p) {
    uint32_t a;
    asm("{ .reg .u64 t; cvta.to.shared.u64 t, %1; cvt.u32.u64 %0, t; }"
        : "=r"(a) : "l"(p));
    return a;
}
__device__ __forceinline__ void ldsm4(uint32_t* r, uint32_t addr) {
    asm volatile("ldmatrix.sync.aligned.m8n8.x4.shared.b16 {%0,%1,%2,%3}, [%4];"
        : "=r"(r[0]), "=r"(r[1]), "=r"(r[2]), "=r"(r[3]) : "r"(addr));
}
__device__ __forceinline__ void ldsm2(uint32_t* r, uint32_t addr) {
    asm volatile("ldmatrix.sync.aligned.m8n8.x2.shared.b16 {%0,%1}, [%2];"
        : "=r"(r[0]), "=r"(r[1]) : "r"(addr));
}
__device__ __forceinline__ void mma16816(float* c, const uint32_t* a,
                                         uint32_t b0, uint32_t b1) {
    asm volatile(
        "mma.sync.aligned.m16n8k16.row.col.f32.bf16.bf16.f32 "
        "{%0,%1,%2,%3}, {%4,%5,%6,%7}, {%8,%9}, {%0,%1,%2,%3};"
        : "+f"(c[0]), "+f"(c[1]), "+f"(c[2]), "+f"(c[3])
        : "r"(a[0]), "r"(a[1]), "r"(a[2]), "r"(a[3]), "r"(b0), "r"(b1));
}
__device__ __forceinline__ void split_store(char* sm, int off_hi, int off_lo,
                                            int boff, float4 v) {
    __nv_bfloat162 h01 = __floats2bfloat162_rn(v.x, v.y);
    __nv_bfloat162 h23 = __floats2bfloat162_rn(v.z, v.w);
    *(uint2*)(sm + off_hi + boff) = make_uint2(*(uint32_t*)&h01, *(uint32_t*)&h23);
    float l0 = v.x - __bfloat162float(__low2bfloat16(h01));
    float l1 = v.y - __bfloat162float(__high2bfloat16(h01));
    float l2 = v.z - __bfloat162float(__low2bfloat16(h23));
    float l3 = v.w - __bfloat162float(__high2bfloat16(h23));
    __nv_bfloat162 s01 = __floats2bfloat162_rn(l0, l1);
    __nv_bfloat162 s23 = __floats2bfloat162_rn(l2, l3);
    *(uint2*)(sm + off_lo + boff) = make_uint2(*(uint32_t*)&s01, *(uint32_t*)&s23);
}
__device__ __forceinline__ float sigmoidf_(float v) {
    return 1.0f / (1.0f + __expf(-v));
}
__device__ __forceinline__ float tanh_ap(float v) {
    float r;
    asm("tanh.approx.f32 %0, %1;" : "=f"(r) : "f"(v));
    return r;
}

__global__ void __launch_bounds__(NTH, 1)
gru_fused_tc(const float* __restrict__ x,
             const float* __restrict__ w_ih,
             const float* __restrict__ w_hh,
             const float* __restrict__ b_ih,
             const float* __restrict__ b_hh,
             const float* __restrict__ fc_w,
             const float* __restrict__ fc_b,
             float* __restrict__ out) {
    extern __shared__ char sm[];
    const uint32_t sb = smem_u32(sm);
    const int tid = threadIdx.x;
    const int w   = tid >> 5;
    const int l   = tid & 31;
    const int r0  = blockIdx.x * ROWS;

    // ---- per-lane gate columns & biases ----
    const int u0 = 8 * w + 2 * (l & 3);     // this lane's first gate unit
    float brz_r[2], brz_z[2], bn_x[2], bn_h[2];
    #pragma unroll
    for (int j = 0; j < 2; ++j) {
        brz_r[j] = b_ih[u0 + j]       + b_hh[u0 + j];
        brz_z[j] = b_ih[64 + u0 + j]  + b_hh[64 + u0 + j];
        bn_x[j]  = b_ih[128 + u0 + j];
        bn_h[j]  = b_hh[128 + u0 + j];
    }

    // ---- weights -> smem hi/lo ----
    {
        const float4* w4 = (const float4*)w_ih;       // 192 x 32 f4
        #pragma unroll
        for (int j = 0; j < 24; ++j) {
            int idx = j * 256 + tid;
            int row = idx >> 5, c4 = idx & 31;
            split_store(sm, WIH_H, WIH_L, row * 272 + c4 * 8, w4[idx]);
        }
        const float4* v4 = (const float4*)w_hh;       // 192 x 16 f4
        #pragma unroll
        for (int j = 0; j < 12; ++j) {
            int idx = j * 256 + tid;
            int row = idx >> 4, c4 = idx & 15;
            split_store(sm, WHH_H, WHH_L, row * 144 + c4 * 8, v4[idx]);
        }
        // zero h bf16 buffers (both hi/lo, both parities)
        for (int i = tid; i < (4 * HSZ) / 4; i += NTH)
            *(uint32_t*)(sm + HBB + i * 4) = 0u;
    }
    __syncthreads();

    // ---- load resident B fragments (warp w owns n-tiles {w, w+8, w+16}) ----
    const int lq = l & 15;
    uint32_t wihH[3][8][2], wihL[3][8][2], whhH[3][4][2], whhL[3][4][2];
    #pragma unroll
    for (int g = 0; g < 3; ++g) {
        const uint32_t rbase = (uint32_t)((g * 64 + 8 * w + (lq & 7)));
        #pragma unroll
        for (int ks = 0; ks < 8; ++ks) {
            uint32_t off = rbase * 272 + ks * 32 + (lq >> 3) * 16;
            ldsm2(wihH[g][ks], sb + WIH_H + off);
            ldsm2(wihL[g][ks], sb + WIH_L + off);
        }
        #pragma unroll
        for (int ks = 0; ks < 4; ++ks) {
            uint32_t off = rbase * 144 + ks * 32 + (lq >> 3) * 16;
            ldsm2(whhH[g][ks], sb + WHH_H + off);
            ldsm2(whhL[g][ks], sb + WHH_L + off);
        }
    }

    // ---- A-fragment lane addresses ----
    const int mrow  = (l & 7) + ((l >> 3) & 1) * 8;
    const int khalf = (l >> 4) & 1;
    const uint32_t aX = (uint32_t)(mrow * 272 + khalf * 16);
    const uint32_t aH = (uint32_t)(mrow * 144 + khalf * 16);

    // ---- x prefetch mapping: 16 rows x 32 f4 per step, 2 f4/thread ----
    const int pr  = tid >> 4;
    const int pc  = (tid & 15) * 2;
    const float4* x4 = (const float4*)x;
    const size_t xrow = (size_t)(r0 + pr) * (Tn * Fn / 4);

    // preload + convert x for t=0 into buf 0
    {
        float4 v0 = x4[xrow + pc];
        float4 v1 = x4[xrow + pc + 1];
        split_store(sm, XB, XB + XLO, pr * 272 + pc * 8, v0);
        split_store(sm, XB, XB + XLO, pr * 272 + (pc + 1) * 8, v1);
    }
    __syncthreads();

    const int r_l = l >> 2;
    float hold[4] = {0.f, 0.f, 0.f, 0.f};

    for (int t = 0; t < Tn; ++t) {
        const int cur = t & 1, nxt = cur ^ 1;

        // issue gmem loads for x(t+1)
        float4 p0, p1;
        const bool pf = (t + 1 < Tn);
        if (pf) {
            p0 = x4[xrow + (size_t)(t + 1) * 32 + pc];
            p1 = x4[xrow + (size_t)(t + 1) * 32 + pc + 1];
        }

        float accR[4]  = {0.f, 0.f, 0.f, 0.f};
        float accZ[4]  = {0.f, 0.f, 0.f, 0.f};
        float accNx[4] = {0.f, 0.f, 0.f, 0.f};
        float accNh[4] = {0.f, 0.f, 0.f, 0.f};

        // ---- gx: x(16x128) @ w_ih^T, 8 k-steps, 3 split terms ----
        const uint32_t xh = sb + XB + cur * XSZ + aX;
        const uint32_t xl = xh + XLO;
        #pragma unroll
        for (int ks = 0; ks < 8; ++ks) {
            uint32_t ah[4], al[4];
            ldsm4(ah, xh + ks * 32);
            ldsm4(al, xl + ks * 32);
            mma16816(accR,  ah, wihH[0][ks][0], wihH[0][ks][1]);
            mma16816(accZ,  ah, wihH[1][ks][0], wihH[1][ks][1]);
            mma16816(accNx, ah, wihH[2][ks][0], wihH[2][ks][1]);
            mma16816(accR,  ah, wihL[0][ks][0], wihL[0][ks][1]);
            mma16816(accZ,  ah, wihL[1][ks][0], wihL[1][ks][1]);
            mma16816(accNx, ah, wihL[2][ks][0], wihL[2][ks][1]);
            mma16816(accR,  al, wihH[0][ks][0], wihH[0][ks][1]);
            mma16816(accZ,  al, wihH[1][ks][0], wihH[1][ks][1]);
            mma16816(accNx, al, wihH[2][ks][0], wihH[2][ks][1]);
        }

        // ---- gh: h(16x64) @ w_hh^T, 4 k-steps, 3 split terms ----
        const uint32_t hh = sb + HBB + cur * HSZ + aH;
        const uint32_t hl = hh + HLO;
        #pragma unroll
        for (int ks = 0; ks < 4; ++ks) {
            uint32_t ah[4], al[4];
            ldsm4(ah, hh + ks * 32);
            ldsm4(al, hl + ks * 32);
            mma16816(accR,  ah, whhH[0][ks][0], whhH[0][ks][1]);
            mma16816(accZ,  ah, whhH[1][ks][0], whhH[1][ks][1]);
            mma16816(accNh, ah, whhH[2][ks][0], whhH[2][ks][1]);
            mma16816(accR,  ah, whhL[0][ks][0], whhL[0][ks][1]);
            mma16816(accZ,  ah, whhL[1][ks][0], whhL[1][ks][1]);
            mma16816(accNh, ah, whhL[2][ks][0], whhL[2][ks][1]);
            mma16816(accR,  al, whhH[0][ks][0], whhH[0][ks][1]);
            mma16816(accZ,  al, whhH[1][ks][0], whhH[1][ks][1]);
            mma16816(accNh, al, whhH[2][ks][0], whhH[2][ks][1]);
        }

        // ---- gates + h update (4 (row,u) pairs per lane) ----
        float hn[4];
        #pragma unroll
        for (int i = 0; i < 2; ++i) {
            #pragma unroll
            for (int j = 0; j < 2; ++j) {
                int idx = 2 * i + j;
                float rr = sigmoidf_(accR[idx] + brz_r[j]);
                float zz = sigmoidf_(accZ[idx] + brz_z[j]);
                float nn = tanh_ap(accNx[idx] + bn_x[j]
                                   + rr * (accNh[idx] + bn_h[j]));
                hn[idx] = (1.0f - zz) * nn + zz * hold[idx];
                hold[idx] = hn[idx];
            }
        }

        // ---- convert + store x(t+1) into nxt buffer ----
        if (pf) {
            split_store(sm, XB + nxt * XSZ, XB + XLO + nxt * XSZ,
                        pr * 272 + pc * 8, p0);
            split_store(sm, XB + nxt * XSZ, XB + XLO + nxt * XSZ,
                        pr * 272 + (pc + 1) * 8, p1);
        }

        // ---- store h_new bf16 hi/lo into nxt buffer ----
        #pragma unroll
        for (int i = 0; i < 2; ++i) {
            int row = r_l + 8 * i;
            float a0 = hn[2 * i], a1 = hn[2 * i + 1];
            __nv_bfloat162 hb2 = __floats2bfloat162_rn(a0, a1);
            *(uint32_t*)(sm + HBB + nxt * HSZ + row * 144 + u0 * 2) =
                *(uint32_t*)&hb2;
            float l0 = a0 - __bfloat162float(__low2bfloat16(hb2));
            float l1 = a1 - __bfloat162float(__high2bfloat16(hb2));
            __nv_bfloat162 lb2 = __floats2bfloat162_rn(l0, l1);
            *(uint32_t*)(sm + HBB + HLO + nxt * HSZ + row * 144 + u0 * 2) =
                *(uint32_t*)&lb2;
        }

        __syncthreads();
    }

    // ---- final FC: write h_last fp32 to smem, reduce ----
    float* hf = (float*)(sm + HF);
    #pragma unroll
    for (int i = 0; i < 2; ++i) {
        int row = r_l + 8 * i;
        hf[row * 68 + u0]     = hold[2 * i];
        hf[row * 68 + u0 + 1] = hold[2 * i + 1];
    }
    __syncthreads();
    if (tid < ROWS) {
        float s = fc_b[0];
        #pragma unroll 8
        for (int j = 0; j < Hn; ++j)
            s += hf[tid * 68 + j] * fc_w[j];
        out[r0 + tid] = s;
    }
}

extern "C" void kernel_launch(void* const* d_in, const int* in_sizes, int n_in,
                              void* d_out, int out_size) {
    const float* x    = (const float*)d_in[0];
    const float* w_ih = (const float*)d_in[1];
    const float* w_hh = (const float*)d_in[2];
    const float* b_ih = (const float*)d_in[3];
    const float* b_hh = (const float*)d_in[4];
    const float* fc_w = (const float*)d_in[5];
    const float* fc_b = (const float*)d_in[6];
    float* out = (float*)d_out;

    cudaFuncSetAttribute(gru_fused_tc,
                         cudaFuncAttributeMaxDynamicSharedMemorySize, SMEMB);
    gru_fused_tc<<<Bn / ROWS, NTH, SMEMB>>>(
        x, w_ih, w_hh, b_ih, b_hh, fc_w, fc_b, out);
}

// round 7
// speedup vs baseline: 4.3801x; 1.4837x over previous
#include <cuda_runtime.h>
#include <cuda_bf16.h>
#include <cstdint>

// ============================================================================
// Fully-fused tensor-core GRU, software-pipelined: gx(t+1) MMAs interleave
// with the serial gh(t) chain. B=2048, T=256, F=128, H=64.
// 128 blocks x 256 threads; block = 16 batch rows.
// ============================================================================

#define Bn 2048
#define Tn 256
#define Fn 128
#define Hn 64
#define ROWS 16
#define NTH 256

// smem offsets (bytes)
#define WIH_H 0                 // 192 x 272
#define WIH_L 52224
#define WHH_H 104448            // 192 x 144
#define WHH_L 132096
#define XB    159744            // x bf16: hi bufs [2], then lo bufs [2], 4352 each
#define XSZ   4352
#define XLO   8704
#define HBB   177152            // h bf16: hi bufs [2], then lo bufs [2], 2304 each
#define HSZ   2304
#define HLO   4608
#define HF    186368            // fp32 h_last: 16 x 68
#define SMEMB 190720

__device__ __forceinline__ uint32_t smem_u32(const void* p) {
    uint32_t a;
    asm("{ .reg .u64 t; cvta.to.shared.u64 t, %1; cvt.u32.u64 %0, t; }"
        : "=r"(a) : "l"(p));
    return a;
}
__device__ __forceinline__ void ldsm4(uint32_t* r, uint32_t addr) {
    asm volatile("ldmatrix.sync.aligned.m8n8.x4.shared.b16 {%0,%1,%2,%3}, [%4];"
        : "=r"(r[0]), "=r"(r[1]), "=r"(r[2]), "=r"(r[3]) : "r"(addr));
}
__device__ __forceinline__ void ldsm2(uint32_t* r, uint32_t addr) {
    asm volatile("ldmatrix.sync.aligned.m8n8.x2.shared.b16 {%0,%1}, [%2];"
        : "=r"(r[0]), "=r"(r[1]) : "r"(addr));
}
__device__ __forceinline__ void mma16816(float* c, const uint32_t* a,
                                         uint32_t b0, uint32_t b1) {
    asm volatile(
        "mma.sync.aligned.m16n8k16.row.col.f32.bf16.bf16.f32 "
        "{%0,%1,%2,%3}, {%4,%5,%6,%7}, {%8,%9}, {%0,%1,%2,%3};"
        : "+f"(c[0]), "+f"(c[1]), "+f"(c[2]), "+f"(c[3])
        : "r"(a[0]), "r"(a[1]), "r"(a[2]), "r"(a[3]), "r"(b0), "r"(b1));
}
__device__ __forceinline__ void split_store(char* sm, int off_hi, int off_lo,
                                            int boff, float4 v) {
    __nv_bfloat162 h01 = __floats2bfloat162_rn(v.x, v.y);
    __nv_bfloat162 h23 = __floats2bfloat162_rn(v.z, v.w);
    *(uint2*)(sm + off_hi + boff) = make_uint2(*(uint32_t*)&h01, *(uint32_t*)&h23);
    float l0 = v.x - __bfloat162float(__low2bfloat16(h01));
    float l1 = v.y - __bfloat162float(__high2bfloat16(h01));
    float l2 = v.z - __bfloat162float(__low2bfloat16(h23));
    float l3 = v.w - __bfloat162float(__high2bfloat16(h23));
    __nv_bfloat162 s01 = __floats2bfloat162_rn(l0, l1);
    __nv_bfloat162 s23 = __floats2bfloat162_rn(l2, l3);
    *(uint2*)(sm + off_lo + boff) = make_uint2(*(uint32_t*)&s01, *(uint32_t*)&s23);
}
__device__ __forceinline__ float tanh_ap(float v) {
    float r;
    asm("tanh.approx.f32 %0, %1;" : "=f"(r) : "f"(v));
    return r;
}
__device__ __forceinline__ float sig_t(float v) {    // sigmoid via tanh
    return fmaf(0.5f, tanh_ap(0.5f * v), 0.5f);
}

__global__ void __launch_bounds__(NTH, 1)
gru_fused_tc(const float* __restrict__ x,
             const float* __restrict__ w_ih,
             const float* __restrict__ w_hh,
             const float* __restrict__ b_ih,
             const float* __restrict__ b_hh,
             const float* __restrict__ fc_w,
             const float* __restrict__ fc_b,
             float* __restrict__ out) {
    extern __shared__ char sm[];
    const uint32_t sb = smem_u32(sm);
    const int tid = threadIdx.x;
    const int w   = tid >> 5;
    const int l   = tid & 31;
    const int r0  = blockIdx.x * ROWS;

    // per-lane gate columns & biases
    const int u0 = 8 * w + 2 * (l & 3);
    float brz_r[2], brz_z[2], bn_x[2], bn_h[2];
    #pragma unroll
    for (int j = 0; j < 2; ++j) {
        brz_r[j] = b_ih[u0 + j]      + b_hh[u0 + j];
        brz_z[j] = b_ih[64 + u0 + j] + b_hh[64 + u0 + j];
        bn_x[j]  = b_ih[128 + u0 + j];
        bn_h[j]  = b_hh[128 + u0 + j];
    }

    // weights -> smem hi/lo
    {
        const float4* w4 = (const float4*)w_ih;
        #pragma unroll
        for (int j = 0; j < 24; ++j) {
            int idx = j * 256 + tid;
            int row = idx >> 5, c4 = idx & 31;
            split_store(sm, WIH_H, WIH_L, row * 272 + c4 * 8, w4[idx]);
        }
        const float4* v4 = (const float4*)w_hh;
        #pragma unroll
        for (int j = 0; j < 12; ++j) {
            int idx = j * 256 + tid;
            int row = idx >> 4, c4 = idx & 15;
            split_store(sm, WHH_H, WHH_L, row * 144 + c4 * 8, v4[idx]);
        }
        for (int i = tid; i < (4 * HSZ) / 4; i += NTH)
            *(uint32_t*)(sm + HBB + i * 4) = 0u;
    }
    __syncthreads();

    // resident B fragments (warp w owns n-tiles {w, w+8, w+16})
    const int lq = l & 15;
    uint32_t wihH[3][8][2], wihL[3][8][2], whhH[3][4][2], whhL[3][4][2];
    #pragma unroll
    for (int g = 0; g < 3; ++g) {
        const uint32_t rbase = (uint32_t)(g * 64 + 8 * w + (lq & 7));
        #pragma unroll
        for (int ks = 0; ks < 8; ++ks) {
            uint32_t off = rbase * 272 + ks * 32 + (lq >> 3) * 16;
            ldsm2(wihH[g][ks], sb + WIH_H + off);
            ldsm2(wihL[g][ks], sb + WIH_L + off);
        }
        #pragma unroll
        for (int ks = 0; ks < 4; ++ks) {
            uint32_t off = rbase * 144 + ks * 32 + (lq >> 3) * 16;
            ldsm2(whhH[g][ks], sb + WHH_H + off);
            ldsm2(whhL[g][ks], sb + WHH_L + off);
        }
    }

    // A-fragment lane addresses
    const int mrow  = (l & 7) + ((l >> 3) & 1) * 8;
    const int khalf = (l >> 4) & 1;
    const uint32_t aX = (uint32_t)(mrow * 272 + khalf * 16);
    const uint32_t aH = (uint32_t)(mrow * 144 + khalf * 16);

    // x prefetch mapping: 16 rows x 32 f4 per step, 2 f4/thread
    const int pr = tid >> 4;
    const int pc = (tid & 15) * 2;
    const float4* x4 = (const float4*)x;
    const size_t xrow = (size_t)(r0 + pr) * (Tn * Fn / 4);

    // preload x(0)->buf0, x(1)->buf1
    {
        float4 v0 = x4[xrow + pc];
        float4 v1 = x4[xrow + pc + 1];
        split_store(sm, XB, XB + XLO, pr * 272 + pc * 8, v0);
        split_store(sm, XB, XB + XLO, pr * 272 + (pc + 1) * 8, v1);
        v0 = x4[xrow + 32 + pc];
        v1 = x4[xrow + 32 + pc + 1];
        split_store(sm, XB + XSZ, XB + XLO + XSZ, pr * 272 + pc * 8, v0);
        split_store(sm, XB + XSZ, XB + XLO + XSZ, pr * 272 + (pc + 1) * 8, v1);
    }
    __syncthreads();

    const int r_l = l >> 2;
    float hold[4] = {0.f, 0.f, 0.f, 0.f};

    // ---- prologue: gx(0) from buf0, biases folded into init ----
    float gxR[4], gxZ[4], gxNx[4];
    #pragma unroll
    for (int i = 0; i < 4; ++i) {
        gxR[i] = brz_r[i & 1]; gxZ[i] = brz_z[i & 1]; gxNx[i] = bn_x[i & 1];
    }
    {
        const uint32_t xh = sb + XB + aX;
        const uint32_t xl = xh + XLO;
        #pragma unroll
        for (int ks = 0; ks < 8; ++ks) {
            uint32_t ah[4], al[4];
            ldsm4(ah, xh + ks * 32);
            ldsm4(al, xl + ks * 32);
            mma16816(gxR,  ah, wihH[0][ks][0], wihH[0][ks][1]);
            mma16816(gxZ,  ah, wihH[1][ks][0], wihH[1][ks][1]);
            mma16816(gxNx, ah, wihH[2][ks][0], wihH[2][ks][1]);
            mma16816(gxR,  ah, wihL[0][ks][0], wihL[0][ks][1]);
            mma16816(gxZ,  ah, wihL[1][ks][0], wihL[1][ks][1]);
            mma16816(gxNx, ah, wihL[2][ks][0], wihL[2][ks][1]);
            mma16816(gxR,  al, wihH[0][ks][0], wihH[0][ks][1]);
            mma16816(gxZ,  al, wihH[1][ks][0], wihH[1][ks][1]);
            mma16816(gxNx, al, wihH[2][ks][0], wihH[2][ks][1]);
        }
    }

    for (int t = 0; t < Tn; ++t) {
        const int cur = t & 1, nxt = cur ^ 1;

        // prefetch x(t+2) from gmem
        float4 p0, p1;
        const bool pf2 = (t + 2 < Tn);
        if (pf2) {
            p0 = x4[xrow + (size_t)(t + 2) * 32 + pc];
            p1 = x4[xrow + (size_t)(t + 2) * 32 + pc + 1];
        }

        // gh accumulators (bn_h folded) and gx(t+1) accumulators (biases folded)
        float ghR[4], ghZ[4], ghNh[4];
        float gxR2[4], gxZ2[4], gxNx2[4];
        #pragma unroll
        for (int i = 0; i < 4; ++i) {
            ghR[i] = 0.f; ghZ[i] = 0.f; ghNh[i] = bn_h[i & 1];
            gxR2[i] = brz_r[i & 1]; gxZ2[i] = brz_z[i & 1]; gxNx2[i] = bn_x[i & 1];
        }

        const uint32_t xh = sb + XB + nxt * XSZ + aX;   // x(t+1)
        const uint32_t xl = xh + XLO;
        const uint32_t hh = sb + HBB + cur * HSZ + aH;  // h(t)
        const uint32_t hl = hh + HLO;

        // interleaved: per q, gh kstep q (serial chain) + gx ksteps 2q,2q+1 (filler)
        #pragma unroll
        for (int q = 0; q < 4; ++q) {
            uint32_t hah[4], hal[4];
            ldsm4(hah, hh + q * 32);
            ldsm4(hal, hl + q * 32);
            #pragma unroll
            for (int s = 0; s < 2; ++s) {
                const int ks = 2 * q + s;
                uint32_t ah[4], al[4];
                ldsm4(ah, xh + ks * 32);
                ldsm4(al, xl + ks * 32);
                mma16816(gxR2,  ah, wihH[0][ks][0], wihH[0][ks][1]);
                mma16816(gxZ2,  ah, wihH[1][ks][0], wihH[1][ks][1]);
                mma16816(gxNx2, ah, wihH[2][ks][0], wihH[2][ks][1]);
                mma16816(gxR2,  ah, wihL[0][ks][0], wihL[0][ks][1]);
                mma16816(gxZ2,  ah, wihL[1][ks][0], wihL[1][ks][1]);
                mma16816(gxNx2, ah, wihL[2][ks][0], wihL[2][ks][1]);
                mma16816(gxR2,  al, wihH[0][ks][0], wihH[0][ks][1]);
                mma16816(gxZ2,  al, wihH[1][ks][0], wihH[1][ks][1]);
                mma16816(gxNx2, al, wihH[2][ks][0], wihH[2][ks][1]);
            }
            mma16816(ghR,  hah, whhH[0][q][0], whhH[0][q][1]);
            mma16816(ghZ,  hah, whhH[1][q][0], whhH[1][q][1]);
            mma16816(ghNh, hah, whhH[2][q][0], whhH[2][q][1]);
            mma16816(ghR,  hah, whhL[0][q][0], whhL[0][q][1]);
            mma16816(ghZ,  hah, whhL[1][q][0], whhL[1][q][1]);
            mma16816(ghNh, hah, whhL[2][q][0], whhL[2][q][1]);
            mma16816(ghR,  hal, whhH[0][q][0], whhH[0][q][1]);
            mma16816(ghZ,  hal, whhH[1][q][0], whhH[1][q][1]);
            mma16816(ghNh, hal, whhH[2][q][0], whhH[2][q][1]);
        }

        // gates + h update (biases already inside accumulators)
        #pragma unroll
        for (int idx = 0; idx < 4; ++idx) {
            float rr = sig_t(ghR[idx] + gxR[idx]);
            float zz = sig_t(ghZ[idx] + gxZ[idx]);
            float nn = tanh_ap(gxNx[idx] + rr * ghNh[idx]);
            hold[idx] = (1.0f - zz) * nn + zz * hold[idx];
        }

        // store x(t+2) into buffer parity cur (x(t) is dead)
        if (pf2) {
            split_store(sm, XB + cur * XSZ, XB + XLO + cur * XSZ,
                        pr * 272 + pc * 8, p0);
            split_store(sm, XB + cur * XSZ, XB + XLO + cur * XSZ,
                        pr * 272 + (pc + 1) * 8, p1);
        }

        // store h(t+1) bf16 hi/lo into nxt buffer
        #pragma unroll
        for (int i = 0; i < 2; ++i) {
            int row = r_l + 8 * i;
            float a0 = hold[2 * i], a1 = hold[2 * i + 1];
            __nv_bfloat162 hb2 = __floats2bfloat162_rn(a0, a1);
            *(uint32_t*)(sm + HBB + nxt * HSZ + row * 144 + u0 * 2) =
                *(uint32_t*)&hb2;
            float l0 = a0 - __bfloat162float(__low2bfloat16(hb2));
            float l1 = a1 - __bfloat162float(__high2bfloat16(hb2));
            __nv_bfloat162 lb2 = __floats2bfloat162_rn(l0, l1);
            *(uint32_t*)(sm + HBB + HLO + nxt * HSZ + row * 144 + u0 * 2) =
                *(uint32_t*)&lb2;
        }

        // rotate gx pipeline
        #pragma unroll
        for (int i = 0; i < 4; ++i) {
            gxR[i] = gxR2[i]; gxZ[i] = gxZ2[i]; gxNx[i] = gxNx2[i];
        }

        __syncthreads();
    }

    // final FC
    float* hf = (float*)(sm + HF);
    #pragma unroll
    for (int i = 0; i < 2; ++i) {
        int row = r_l + 8 * i;
        hf[row * 68 + u0]     = hold[2 * i];
        hf[row * 68 + u0 + 1] = hold[2 * i + 1];
    }
    __syncthreads();
    if (tid < ROWS) {
        float s = fc_b[0];
        #pragma unroll 8
        for (int j = 0; j < Hn; ++j)
            s += hf[tid * 68 + j] * fc_w[j];
        out[r0 + tid] = s;
    }
}

extern "C" void kernel_launch(void* const* d_in, const int* in_sizes, int n_in,
                              void* d_out, int out_size) {
    const float* x    = (const float*)d_in[0];
    const float* w_ih = (const float*)d_in[1];
    const float* w_hh = (const float*)d_in[2];
    const float* b_ih = (const float*)d_in[3];
    const float* b_hh = (const float*)d_in[4];
    const float* fc_w = (const float*)d_in[5];
    const float* fc_b = (const float*)d_in[6];
    float* out = (float*)d_out;

    cudaFuncSetAttribute(gru_fused_tc,
                         cudaFuncAttributeMaxDynamicSharedMemorySize, SMEMB);
    gru_fused_tc<<<Bn / ROWS, NTH, SMEMB>>>(
        x, w_ih, w_hh, b_ih, b_hh, fc_w, fc_b, out);
}